// round 16
// baseline (speedup 1.0000x reference)
#include <cuda_runtime.h>
#include <cuda_fp16.h>
#include <cstdint>
#include <math.h>

#define D_MODEL 1024
#define NHEADS  16
#define HDIM    64
#define BB      2
#define LL      2048
#define MROWS   (BB * LL)   // 4096
#define MD      (MROWS * D_MODEL)
#define DD      (D_MODEL * D_MODEL)

// ---------------- scratch (allocation-free rule: __device__ globals) ---------
__device__ __half g_INh[3 * MD];   // split q,k,v inputs (hi)
__device__ __half g_INl[3 * MD];   // (lo)
__device__ __half g_W3[3 * DD];    // Wq,Wk,Wv single fp16
__device__ __half g_Wo[DD];        // Wo single fp16
__device__ __half g_Qh[MD];        // Q split (A side of QK^T)
__device__ __half g_Ql[MD];
__device__ __half g_K[MD];         // K single (B side)
__device__ __half g_V[MD];         // V single (B side)
__device__ __half g_Ahi[MD];       // ctx split (A side of out-proj)
__device__ __half g_Alo[MD];

// ---------------------------------------------------------------------------
// baseline-PTX helpers (sm_80-era; tcgen05/TMA rejected at compute_103)
// ---------------------------------------------------------------------------
static __device__ __forceinline__ uint32_t smem_u32(const void* p) {
    uint32_t a;
    asm("{ .reg .u64 t; cvta.to.shared.u64 t, %1; cvt.u32.u64 %0, t; }"
        : "=r"(a) : "l"(p));
    return a;
}
static __device__ __forceinline__ void cp_async16(uint32_t saddr, const void* gaddr) {
    asm volatile("cp.async.cg.shared.global [%0], [%1], 16;" :: "r"(saddr), "l"(gaddr));
}
static __device__ __forceinline__ void cp_commit() {
    asm volatile("cp.async.commit_group;" ::: "memory");
}
template <int N>
static __device__ __forceinline__ void cp_wait() {
    asm volatile("cp.async.wait_group %0;" :: "n"(N) : "memory");
}
static __device__ __forceinline__ void ldm_x4(uint32_t* r, uint32_t saddr) {
    asm volatile("ldmatrix.sync.aligned.m8n8.x4.shared.b16 {%0,%1,%2,%3}, [%4];"
                 : "=r"(r[0]), "=r"(r[1]), "=r"(r[2]), "=r"(r[3]) : "r"(saddr));
}
static __device__ __forceinline__ void ldm_x4_t(uint32_t* r, uint32_t saddr) {
    asm volatile("ldmatrix.sync.aligned.m8n8.x4.trans.shared.b16 {%0,%1,%2,%3}, [%4];"
                 : "=r"(r[0]), "=r"(r[1]), "=r"(r[2]), "=r"(r[3]) : "r"(saddr));
}
static __device__ __forceinline__ void mma_f16(float* c, const uint32_t* a,
                                               uint32_t b0, uint32_t b1) {
    asm volatile(
        "mma.sync.aligned.m16n8k16.row.col.f32.f16.f16.f32 "
        "{%0,%1,%2,%3}, {%4,%5,%6,%7}, {%8,%9}, {%0,%1,%2,%3};"
        : "+f"(c[0]), "+f"(c[1]), "+f"(c[2]), "+f"(c[3])
        : "r"(a[0]), "r"(a[1]), "r"(a[2]), "r"(a[3]), "r"(b0), "r"(b1));
}

// ---------------------------------------------------------------------------
// fp32 -> fp16 hi/lo split (batched over blockIdx.z) and single convert
// ---------------------------------------------------------------------------
__global__ void split3_f16(const float4* __restrict__ p0,
                           const float4* __restrict__ p1,
                           const float4* __restrict__ p2,
                           __half2* __restrict__ hi, __half2* __restrict__ lo,
                           int n4, size_t zs2)
{
    int i = blockIdx.x * blockDim.x + threadIdx.x;
    if (i >= n4) return;
    const float4* in = (blockIdx.z == 0) ? p0 : (blockIdx.z == 1) ? p1 : p2;
    hi += (size_t)blockIdx.z * zs2;
    lo += (size_t)blockIdx.z * zs2;
    float4 x = in[i];
    __half2 h01 = __floats2half2_rn(x.x, x.y);
    __half2 h23 = __floats2half2_rn(x.z, x.w);
    __half2 l01 = __floats2half2_rn(x.x - __low2float(h01), x.y - __high2float(h01));
    __half2 l23 = __floats2half2_rn(x.z - __low2float(h23), x.w - __high2float(h23));
    hi[2 * i] = h01; hi[2 * i + 1] = h23;
    lo[2 * i] = l01; lo[2 * i + 1] = l23;
}

__global__ void cvt3_f16(const float4* __restrict__ p0,
                         const float4* __restrict__ p1,
                         const float4* __restrict__ p2,
                         __half2* __restrict__ out, int n4, size_t zs2)
{
    int i = blockIdx.x * blockDim.x + threadIdx.x;
    if (i >= n4) return;
    const float4* in = (blockIdx.z == 0) ? p0 : (blockIdx.z == 1) ? p1 : p2;
    out += (size_t)blockIdx.z * zs2;
    float4 x = in[i];
    out[2 * i]     = __floats2half2_rn(x.x, x.y);
    out[2 * i + 1] = __floats2half2_rn(x.z, x.w);
}

// ---------------------------------------------------------------------------
// HMMA GEMM (fp16x2): C = (Ah + Al) @ Bh^T.  CTA 128x256, 512 threads,
// 16 warps (4x4), warp tile 32x64, BK=32, 3-stage cp.async pipeline.
// Smem stage: A: op*10240 + row*80 + c*16 (128 rows, 2 ops)
//             B: 20480 + row*80 + c*16    (256 rows, single)
// stage = 40960 B, 3 stages = 122880 B.
// MODE 0: batched QKV (z=0 -> split Qh/Ql, z=1 -> K single, z=2 -> V single)
// MODE 1: fp32 out + bias (out projection)
// ---------------------------------------------------------------------------
#define STG3   40960
#define GSMEM3 (3 * STG3)

template <int MODE>
__global__ __launch_bounds__(512, 1) void hmma_f16(
    const __half* __restrict__ Ah_, const __half* __restrict__ Al_,
    const __half* __restrict__ B_,
    __half* __restrict__ Qh, __half* __restrict__ Ql,
    __half* __restrict__ Ko, __half* __restrict__ Vo,
    float* __restrict__ C, const float* __restrict__ bias)
{
    extern __shared__ char sm[];
    const uint32_t sb = smem_u32(sm);
    const int t = threadIdx.x;
    const int lane = t & 31, wid = t >> 5;
    const int wm = wid & 3, wn = wid >> 2;      // 4x4 warp grid: 32 rows x 64 cols
    const int row0 = blockIdx.y * 128, col0 = blockIdx.x * 256;
    const int z = blockIdx.z;

    const __half* srcA[2] = { Ah_ + (size_t)z * MD + (size_t)row0 * 1024,
                              Al_ + (size_t)z * MD + (size_t)row0 * 1024 };
    const __half* srcB = B_ + (size_t)z * DD + (size_t)col0 * 1024;

    auto load_stage = [&](int s) {
        const int k0 = s * 32;
        const uint32_t sbase = sb + (uint32_t)((s % 3) * STG3);
#pragma unroll
        for (int i = 0; i < 4; i++) {
            int idx = t + i * 512;              // 0..2047
            if (idx < 1024) {                   // A: 2 ops x 128 rows x 4 chunks
                int op = idx >> 9, r = (idx >> 2) & 127, c = idx & 3;
                cp_async16(sbase + op * 10240 + r * 80 + c * 16,
                           srcA[op] + (size_t)r * 1024 + k0 + c * 8);
            } else {                            // B: 256 rows x 4 chunks
                int j = idx - 1024;
                int r = (j >> 2) & 255, c = j & 3;
                cp_async16(sbase + 20480 + r * 80 + c * 16,
                           srcB + (size_t)r * 1024 + k0 + c * 8);
            }
        }
        cp_commit();
    };

    const uint32_t a_lane = (uint32_t)((wm * 32 + (lane & 15)) * 80 + (lane >> 4) * 16);
    const uint32_t b_lane = (uint32_t)((wn * 64 + (lane & 7) + ((lane >> 4) & 1) * 8) * 80
                                       + ((lane >> 3) & 1) * 16);

    float acc[2][8][4];
#pragma unroll
    for (int i = 0; i < 2; i++)
#pragma unroll
        for (int n = 0; n < 8; n++)
#pragma unroll
            for (int j = 0; j < 4; j++) acc[i][n][j] = 0.f;

    load_stage(0);
    load_stage(1);

    for (int s = 0; s < 32; s++) {
        if (s + 2 < 32)      { load_stage(s + 2); cp_wait<2>(); }
        else if (s + 1 < 32) { cp_wait<1>(); }
        else                 { cp_wait<0>(); }
        __syncthreads();

        const uint32_t sbase = sb + (uint32_t)((s % 3) * STG3);
#pragma unroll
        for (int ks = 0; ks < 2; ks++) {
            const uint32_t ksb = ks * 32;
            uint32_t ah[2][4], al[2][4];
#pragma unroll
            for (int i = 0; i < 2; i++) {
                uint32_t base = sbase + a_lane + (uint32_t)(i * 16 * 80) + ksb;
                ldm_x4(ah[i], base);
                ldm_x4(al[i], base + 10240);
            }
#pragma unroll
            for (int p = 0; p < 4; p++) {
                uint32_t b[4];
                ldm_x4(b, sbase + 20480 + b_lane + (uint32_t)(p * 16 * 80) + ksb);
#pragma unroll
                for (int i = 0; i < 2; i++) {
                    mma_f16(acc[i][2 * p],     ah[i], b[0], b[1]);
                    mma_f16(acc[i][2 * p + 1], ah[i], b[2], b[3]);
                    mma_f16(acc[i][2 * p],     al[i], b[0], b[1]);
                    mma_f16(acc[i][2 * p + 1], al[i], b[2], b[3]);
                }
            }
        }
        __syncthreads();
    }

    const int er = lane >> 2, ec = (lane & 3) * 2;
#pragma unroll
    for (int i = 0; i < 2; i++) {
        const int rbase = row0 + wm * 32 + i * 16 + er;
#pragma unroll
        for (int n = 0; n < 8; n++) {
            const int cc = col0 + wn * 64 + n * 8 + ec;
            if (MODE == 0) {
                if (z == 0) {
#pragma unroll
                    for (int half = 0; half < 2; half++) {
                        float v0 = acc[i][n][2 * half], v1 = acc[i][n][2 * half + 1];
                        __half2 hv = __floats2half2_rn(v0, v1);
                        __half2 lv = __floats2half2_rn(v0 - __low2float(hv),
                                                       v1 - __high2float(hv));
                        size_t off = (size_t)(rbase + half * 8) * 1024 + cc;
                        *(__half2*)(Qh + off) = hv;
                        *(__half2*)(Ql + off) = lv;
                    }
                } else {
                    __half* dst = (z == 1) ? Ko : Vo;
#pragma unroll
                    for (int half = 0; half < 2; half++) {
                        size_t off = (size_t)(rbase + half * 8) * 1024 + cc;
                        *(__half2*)(dst + off) =
                            __floats2half2_rn(acc[i][n][2 * half], acc[i][n][2 * half + 1]);
                    }
                }
            } else {
                float b0 = bias[cc], b1 = bias[cc + 1];
                float2 lo_v = make_float2(acc[i][n][0] + b0, acc[i][n][1] + b1);
                float2 hi_v = make_float2(acc[i][n][2] + b0, acc[i][n][3] + b1);
                *(float2*)(C + (size_t)rbase * 1024 + cc)       = lo_v;
                *(float2*)(C + (size_t)(rbase + 8) * 1024 + cc) = hi_v;
            }
        }
    }
}

// ---------------------------------------------------------------------------
// HMMA flash attention (fp16x2: Q split / K single, P split / V single).
// CTA = (b, h, 128-row q tile); 8 warps, warp = 16 q rows x full 64 kv/d.
// Smem: Qh[128x144] Ql[128x144] | 2 stages x {K,V}[64x144] | mask
// ---------------------------------------------------------------------------
#define APITCH   144
#define AQ_SZ    18432
#define AKV_OFF  (2 * AQ_SZ)               // 36864
#define AKV_STG  18432                     // K 9216 + V 9216
#define AM_OFF   (AKV_OFF + 2 * AKV_STG)   // 73728
#define ATT_SMEM (AM_OFF + 512)

__global__ __launch_bounds__(256, 1) void attn_f16(const int* __restrict__ mask)
{
    extern __shared__ char sm[];
    const uint32_t sb = smem_u32(sm);
    const int t = threadIdx.x, lane = t & 31, w = t >> 5;
    const int q0 = blockIdx.x * 128, h = blockIdx.y, b = blockIdx.z;

    const size_t qoff  = (size_t)(b * LL + q0) * D_MODEL + h * HDIM;
    const size_t kvoff = (size_t)b * LL * D_MODEL + h * HDIM;
    const __half* kvsrc[2] = { g_K + kvoff, g_V + kvoff };

    {   // Q tile (once), committed with kv stage 0
        const __half* qsrc[2] = { g_Qh + qoff, g_Ql + qoff };
#pragma unroll
        for (int i = 0; i < 8; i++) {
            int idx = t + i * 256;
            int arr = idx >> 10, row = (idx >> 3) & 127, c = idx & 7;
            cp_async16(sb + arr * AQ_SZ + row * APITCH + c * 16,
                       qsrc[arr] + (size_t)row * D_MODEL + c * 8);
        }
    }
    auto load_kv = [&](int kt) {
        const uint32_t sbase = sb + AKV_OFF + (kt & 1) * AKV_STG;
#pragma unroll
        for (int i = 0; i < 4; i++) {
            int idx = t + i * 256;              // 0..1023
            int arr = idx >> 9, row = (idx >> 3) & 63, c = idx & 7;
            cp_async16(sbase + arr * 9216 + row * APITCH + c * 16,
                       kvsrc[arr] + (size_t)(kt * 64 + row) * D_MODEL + c * 8);
        }
        if (t < 64) {
            float bv = mask[b * LL + kt * 64 + t] ? 0.f : -1e30f;
            *(float*)(sm + AM_OFF + (kt & 1) * 256 + t * 4) = bv;
        }
        cp_commit();
    };
    load_kv(0);

    uint32_t qh[4][4], ql[4][4];
    float m0 = -1e30f, m1 = -1e30f, l0 = 0.f, l1 = 0.f;
    float O[8][4];
#pragma unroll
    for (int j = 0; j < 8; j++)
#pragma unroll
        for (int r = 0; r < 4; r++) O[j][r] = 0.f;

    const uint32_t a_addr =
        sb + (uint32_t)((w * 16 + (lane & 15)) * APITCH + (lane >> 4) * 16);
    const uint32_t k_lane =
        (uint32_t)(((lane & 7) + ((lane >> 4) & 1) * 8) * APITCH + ((lane >> 3) & 1) * 16);
    const uint32_t v_lane =
        (uint32_t)(((lane & 7) + ((lane >> 3) & 1) * 8) * APITCH + ((lane >> 4) & 1) * 16);

    for (int kt = 0; kt < LL / 64; kt++) {
        if (kt + 1 < LL / 64) { load_kv(kt + 1); cp_wait<1>(); }
        else                  { cp_wait<0>(); }
        __syncthreads();
        if (kt == 0) {
#pragma unroll
            for (int kd = 0; kd < 4; kd++) {
                ldm_x4(qh[kd], a_addr + kd * 32);
                ldm_x4(ql[kd], a_addr + AQ_SZ + kd * 32);
            }
        }
        const uint32_t kvb = sb + AKV_OFF + (kt & 1) * AKV_STG;

        // ---- S = Q K^T (fp16x2: (Qh+Ql) * K) ----
        float sc_[8][4];
#pragma unroll
        for (int j = 0; j < 8; j++)
#pragma unroll
            for (int r = 0; r < 4; r++) sc_[j][r] = 0.f;
#pragma unroll
        for (int kd = 0; kd < 4; kd++) {
#pragma unroll
            for (int g = 0; g < 4; g++) {
                uint32_t kb[4];
                ldm_x4(kb, kvb + k_lane + (uint32_t)(g * 16 * APITCH) + kd * 32);
                mma_f16(sc_[2 * g],     qh[kd], kb[0], kb[1]);
                mma_f16(sc_[2 * g + 1], qh[kd], kb[2], kb[3]);
                mma_f16(sc_[2 * g],     ql[kd], kb[0], kb[1]);
                mma_f16(sc_[2 * g + 1], ql[kd], kb[2], kb[3]);
            }
        }

        // ---- online softmax (rows r0 = lane>>2, r1 = r0+8) ----
        const uint32_t mb = sb + AM_OFF + (uint32_t)((kt & 1) * 256 + (lane & 3) * 8);
        float mt0 = -1e30f, mt1 = -1e30f;
#pragma unroll
        for (int j = 0; j < 8; j++) {
            float bx, by;
            asm volatile("ld.shared.v2.f32 {%0,%1}, [%2];"
                         : "=f"(bx), "=f"(by) : "r"(mb + j * 32));
            sc_[j][0] = fmaf(sc_[j][0], 0.125f, bx);
            sc_[j][1] = fmaf(sc_[j][1], 0.125f, by);
            sc_[j][2] = fmaf(sc_[j][2], 0.125f, bx);
            sc_[j][3] = fmaf(sc_[j][3], 0.125f, by);
            mt0 = fmaxf(mt0, fmaxf(sc_[j][0], sc_[j][1]));
            mt1 = fmaxf(mt1, fmaxf(sc_[j][2], sc_[j][3]));
        }
        mt0 = fmaxf(mt0, __shfl_xor_sync(0xffffffffu, mt0, 1));
        mt0 = fmaxf(mt0, __shfl_xor_sync(0xffffffffu, mt0, 2));
        mt1 = fmaxf(mt1, __shfl_xor_sync(0xffffffffu, mt1, 1));
        mt1 = fmaxf(mt1, __shfl_xor_sync(0xffffffffu, mt1, 2));
        const float m0n = fmaxf(m0, mt0), m1n = fmaxf(m1, mt1);
        const float e0 = __expf(m0 - m0n), e1 = __expf(m1 - m1n);
        m0 = m0n; m1 = m1n;
        float rs0 = 0.f, rs1 = 0.f;
#pragma unroll
        for (int j = 0; j < 8; j++) {
            float p0 = __expf(sc_[j][0] - m0n), p1 = __expf(sc_[j][1] - m0n);
            float p2 = __expf(sc_[j][2] - m1n), p3 = __expf(sc_[j][3] - m1n);
            sc_[j][0] = p0; sc_[j][1] = p1; sc_[j][2] = p2; sc_[j][3] = p3;
            rs0 += p0 + p1; rs1 += p2 + p3;
        }
        rs0 += __shfl_xor_sync(0xffffffffu, rs0, 1);
        rs0 += __shfl_xor_sync(0xffffffffu, rs0, 2);
        rs1 += __shfl_xor_sync(0xffffffffu, rs1, 1);
        rs1 += __shfl_xor_sync(0xffffffffu, rs1, 2);
        l0 = l0 * e0 + rs0; l1 = l1 * e1 + rs1;
#pragma unroll
        for (int j = 0; j < 8; j++) {
            O[j][0] *= e0; O[j][1] *= e0; O[j][2] *= e1; O[j][3] *= e1;
        }

        // ---- O += P V (fp16x2: (Ph+Pl) * V, P packed from registers) ----
#pragma unroll
        for (int tk = 0; tk < 4; tk++) {
            uint32_t pah[4], pal[4];
#pragma unroll
            for (int q = 0; q < 4; q++) {
                int j = 2 * tk + (q >> 1);
                float p0 = sc_[j][(q & 1) * 2], p1 = sc_[j][(q & 1) * 2 + 1];
                __half2 hv = __floats2half2_rn(p0, p1);
                __half2 lv = __floats2half2_rn(p0 - __low2float(hv),
                                               p1 - __high2float(hv));
                pah[q] = *(uint32_t*)&hv;
                pal[q] = *(uint32_t*)&lv;
            }
#pragma unroll
            for (int dg = 0; dg < 4; dg++) {
                uint32_t vb[4];
                ldm_x4_t(vb, kvb + 9216 + v_lane
                             + (uint32_t)(tk * 16 * APITCH) + dg * 32);
                mma_f16(O[2 * dg],     pah, vb[0], vb[1]);
                mma_f16(O[2 * dg + 1], pah, vb[2], vb[3]);
                mma_f16(O[2 * dg],     pal, vb[0], vb[1]);
                mma_f16(O[2 * dg + 1], pal, vb[2], vb[3]);
            }
        }
        __syncthreads();
    }

    // ---- epilogue: normalize, write ctx hi/lo split for the output GEMM ----
    const float inv0 = (m0 > -1e29f && l0 > 0.f) ? 1.f / l0 : 0.f;
    const float inv1 = (m1 > -1e29f && l1 > 0.f) ? 1.f / l1 : 0.f;
    const size_t r0 = (size_t)(b * LL + q0 + w * 16 + (lane >> 2));
    const int cb = h * HDIM + (lane & 3) * 2;
#pragma unroll
    for (int j = 0; j < 8; j++) {
        const int cc = cb + j * 8;
        {
            float v0 = O[j][0] * inv0, v1 = O[j][1] * inv0;
            __half2 hv = __floats2half2_rn(v0, v1);
            __half2 lv = __floats2half2_rn(v0 - __low2float(hv), v1 - __high2float(hv));
            *(__half2*)(g_Ahi + r0 * D_MODEL + cc) = hv;
            *(__half2*)(g_Alo + r0 * D_MODEL + cc) = lv;
        }
        {
            float v0 = O[j][2] * inv1, v1 = O[j][3] * inv1;
            __half2 hv = __floats2half2_rn(v0, v1);
            __half2 lv = __floats2half2_rn(v0 - __low2float(hv), v1 - __high2float(hv));
            *(__half2*)(g_Ahi + (r0 + 8) * D_MODEL + cc) = hv;
            *(__half2*)(g_Alo + (r0 + 8) * D_MODEL + cc) = lv;
        }
    }
}

// ---------------------------------------------------------------------------
extern "C" void kernel_launch(void* const* d_in, const int* in_sizes, int n_in,
                              void* d_out, int out_size)
{
    const float* q    = (const float*)d_in[0];
    const float* k    = (const float*)d_in[1];
    const float* v    = (const float*)d_in[2];
    const int*   mask = (const int*)  d_in[3];
    const float* Wq   = (const float*)d_in[4];
    const float* Wk   = (const float*)d_in[5];
    const float* Wv   = (const float*)d_in[6];
    const float* Wo   = (const float*)d_in[7];
    const float* bo   = (const float*)d_in[8];
    float*       out  = (float*)d_out;

    __half *gINh, *gINl, *gW3, *gWo, *gQh, *gQl, *gK, *gV, *gAhi, *gAlo;
    cudaGetSymbolAddress((void**)&gINh, g_INh);
    cudaGetSymbolAddress((void**)&gINl, g_INl);
    cudaGetSymbolAddress((void**)&gW3, g_W3);
    cudaGetSymbolAddress((void**)&gWo, g_Wo);
    cudaGetSymbolAddress((void**)&gQh, g_Qh);
    cudaGetSymbolAddress((void**)&gQl, g_Ql);
    cudaGetSymbolAddress((void**)&gK, g_K);
    cudaGetSymbolAddress((void**)&gV, g_V);
    cudaGetSymbolAddress((void**)&gAhi, g_Ahi);
    cudaGetSymbolAddress((void**)&gAlo, g_Alo);

    cudaFuncSetAttribute(hmma_f16<0>,
                         cudaFuncAttributeMaxDynamicSharedMemorySize, GSMEM3);
    cudaFuncSetAttribute(hmma_f16<1>,
                         cudaFuncAttributeMaxDynamicSharedMemorySize, GSMEM3);
    cudaFuncSetAttribute(attn_f16,
                         cudaFuncAttributeMaxDynamicSharedMemorySize, ATT_SMEM);

    const int n4i = MD / 4;
    const int n4w = DD / 4;

    // split x,k,v inputs (hi/lo) and convert weights (single fp16)
    split3_f16<<<dim3(n4i / 256, 1, 3), 256>>>(
        (const float4*)q, (const float4*)k, (const float4*)v,
        (__half2*)gINh, (__half2*)gINl, n4i, (size_t)MD / 2);
    cvt3_f16<<<dim3(n4w / 256, 1, 3), 256>>>(
        (const float4*)Wq, (const float4*)Wk, (const float4*)Wv,
        (__half2*)gW3, n4w, (size_t)DD / 2);
    cvt3_f16<<<dim3(n4w / 256, 1, 1), 256>>>(
        (const float4*)Wo, (const float4*)Wo, (const float4*)Wo,
        (__half2*)gWo, n4w, 0);

    // batched Q/K/V projections: grid (4, 32, 3)
    hmma_f16<0><<<dim3(D_MODEL / 256, MROWS / 128, 3), 512, GSMEM3>>>(
        gINh, gINl, gW3, gQh, gQl, gK, gV, nullptr, nullptr);

    // attention (writes ctx split into gAhi/gAlo)
    attn_f16<<<dim3(LL / 128, NHEADS, BB), 256, ATT_SMEM>>>(mask);

    // output projection (fp32 out + bias)
    hmma_f16<1><<<dim3(D_MODEL / 256, MROWS / 128, 1), 512, GSMEM3>>>(
        gAhi, gAlo, gWo, nullptr, nullptr, nullptr, nullptr, out, bo);
}

// round 17
// speedup vs baseline: 1.6111x; 1.6111x over previous
#include <cuda_runtime.h>
#include <cuda_fp16.h>
#include <cstdint>
#include <math.h>

#define D_MODEL 1024
#define NHEADS  16
#define HDIM    64
#define BB      2
#define LL      2048
#define MROWS   (BB * LL)   // 4096
#define MD      (MROWS * D_MODEL)
#define DD      (D_MODEL * D_MODEL)

// ---------------- scratch (allocation-free rule: __device__ globals) ---------
__device__ __half g_INh[3 * MD];   // split q,k,v inputs (hi)
__device__ __half g_INl[3 * MD];   // (lo)
__device__ __half g_W3[3 * DD];    // Wq,Wk,Wv single fp16
__device__ __half g_Wo[DD];        // Wo single fp16
__device__ __half g_Qh[MD];        // Q split (A side of QK^T)
__device__ __half g_Ql[MD];
__device__ __half g_K[MD];         // K single (B side)
__device__ __half g_V[MD];         // V single (B side)
__device__ __half g_Ahi[MD];       // ctx split (A side of out-proj)
__device__ __half g_Alo[MD];

// ---------------------------------------------------------------------------
// baseline-PTX helpers (sm_80-era; tcgen05/TMA rejected at compute_103)
// ---------------------------------------------------------------------------
static __device__ __forceinline__ uint32_t smem_u32(const void* p) {
    uint32_t a;
    asm("{ .reg .u64 t; cvta.to.shared.u64 t, %1; cvt.u32.u64 %0, t; }"
        : "=r"(a) : "l"(p));
    return a;
}
static __device__ __forceinline__ void cp_async16(uint32_t saddr, const void* gaddr) {
    asm volatile("cp.async.cg.shared.global [%0], [%1], 16;" :: "r"(saddr), "l"(gaddr));
}
static __device__ __forceinline__ void cp_commit() {
    asm volatile("cp.async.commit_group;" ::: "memory");
}
template <int N>
static __device__ __forceinline__ void cp_wait() {
    asm volatile("cp.async.wait_group %0;" :: "n"(N) : "memory");
}
static __device__ __forceinline__ void ldm_x4(uint32_t* r, uint32_t saddr) {
    asm volatile("ldmatrix.sync.aligned.m8n8.x4.shared.b16 {%0,%1,%2,%3}, [%4];"
                 : "=r"(r[0]), "=r"(r[1]), "=r"(r[2]), "=r"(r[3]) : "r"(saddr));
}
static __device__ __forceinline__ void ldm_x4_t(uint32_t* r, uint32_t saddr) {
    asm volatile("ldmatrix.sync.aligned.m8n8.x4.trans.shared.b16 {%0,%1,%2,%3}, [%4];"
                 : "=r"(r[0]), "=r"(r[1]), "=r"(r[2]), "=r"(r[3]) : "r"(saddr));
}
static __device__ __forceinline__ void mma_f16(float* c, const uint32_t* a,
                                               uint32_t b0, uint32_t b1) {
    asm volatile(
        "mma.sync.aligned.m16n8k16.row.col.f32.f16.f16.f32 "
        "{%0,%1,%2,%3}, {%4,%5,%6,%7}, {%8,%9}, {%0,%1,%2,%3};"
        : "+f"(c[0]), "+f"(c[1]), "+f"(c[2]), "+f"(c[3])
        : "r"(a[0]), "r"(a[1]), "r"(a[2]), "r"(a[3]), "r"(b0), "r"(b1));
}

// ---------------------------------------------------------------------------
// fp32 -> fp16 hi/lo split (batched over blockIdx.z) and single convert
// ---------------------------------------------------------------------------
__global__ void split3_f16(const float4* __restrict__ p0,
                           const float4* __restrict__ p1,
                           const float4* __restrict__ p2,
                           __half2* __restrict__ hi, __half2* __restrict__ lo,
                           int n4, size_t zs2)
{
    int i = blockIdx.x * blockDim.x + threadIdx.x;
    if (i >= n4) return;
    const float4* in = (blockIdx.z == 0) ? p0 : (blockIdx.z == 1) ? p1 : p2;
    hi += (size_t)blockIdx.z * zs2;
    lo += (size_t)blockIdx.z * zs2;
    float4 x = in[i];
    __half2 h01 = __floats2half2_rn(x.x, x.y);
    __half2 h23 = __floats2half2_rn(x.z, x.w);
    __half2 l01 = __floats2half2_rn(x.x - __low2float(h01), x.y - __high2float(h01));
    __half2 l23 = __floats2half2_rn(x.z - __low2float(h23), x.w - __high2float(h23));
    hi[2 * i] = h01; hi[2 * i + 1] = h23;
    lo[2 * i] = l01; lo[2 * i + 1] = l23;
}

__global__ void cvt3_f16(const float4* __restrict__ p0,
                         const float4* __restrict__ p1,
                         const float4* __restrict__ p2,
                         __half2* __restrict__ out, int n4, size_t zs2)
{
    int i = blockIdx.x * blockDim.x + threadIdx.x;
    if (i >= n4) return;
    const float4* in = (blockIdx.z == 0) ? p0 : (blockIdx.z == 1) ? p1 : p2;
    out += (size_t)blockIdx.z * zs2;
    float4 x = in[i];
    out[2 * i]     = __floats2half2_rn(x.x, x.y);
    out[2 * i + 1] = __floats2half2_rn(x.z, x.w);
}

// ---------------------------------------------------------------------------
// HMMA GEMM (fp16x2): C = (Ah + Al) @ B^T.  CTA 128x128, 256 threads,
// 8 warps (4m x 2n), warp tile 32x64, BK=32, 3-stage cp.async pipeline.
// Sized for 2 CTAs/SM: 256 thr x <=128 regs = half the regfile; smem
// stage = A(2 ops)20480 + B 10240 = 30720 B; 3 stages = 92160 B/CTA.
// MODE 0: batched QKV (z=0 -> split Qh/Ql, z=1 -> K single, z=2 -> V single)
// MODE 1: fp32 out + bias (out projection)
// ---------------------------------------------------------------------------
#define STG3   30720
#define GSMEM3 (3 * STG3)

template <int MODE>
__global__ __launch_bounds__(256, 2) void hmma_f16(
    const __half* __restrict__ Ah_, const __half* __restrict__ Al_,
    const __half* __restrict__ B_,
    __half* __restrict__ Qh, __half* __restrict__ Ql,
    __half* __restrict__ Ko, __half* __restrict__ Vo,
    float* __restrict__ C, const float* __restrict__ bias)
{
    extern __shared__ char sm[];
    const uint32_t sb = smem_u32(sm);
    const int t = threadIdx.x;
    const int lane = t & 31, wid = t >> 5;
    const int wm = wid & 3, wn = wid >> 2;      // 4x2 warp grid: 32 rows x 64 cols
    const int row0 = blockIdx.y * 128, col0 = blockIdx.x * 128;
    const int z = blockIdx.z;

    const __half* srcA[2] = { Ah_ + (size_t)z * MD + (size_t)row0 * 1024,
                              Al_ + (size_t)z * MD + (size_t)row0 * 1024 };
    const __half* srcB = B_ + (size_t)z * DD + (size_t)col0 * 1024;

    auto load_stage = [&](int s) {
        const int k0 = s * 32;
        const uint32_t sbase = sb + (uint32_t)((s % 3) * STG3);
#pragma unroll
        for (int i = 0; i < 6; i++) {
            int idx = t + i * 256;              // 0..1535
            if (idx < 1024) {                   // A: 2 ops x 128 rows x 4 chunks
                int op = idx >> 9, r = (idx >> 2) & 127, c = idx & 3;
                cp_async16(sbase + op * 10240 + r * 80 + c * 16,
                           srcA[op] + (size_t)r * 1024 + k0 + c * 8);
            } else {                            // B: 128 rows x 4 chunks
                int j = idx - 1024;
                int r = (j >> 2) & 127, c = j & 3;
                cp_async16(sbase + 20480 + r * 80 + c * 16,
                           srcB + (size_t)r * 1024 + k0 + c * 8);
            }
        }
        cp_commit();
    };

    const uint32_t a_lane = (uint32_t)((wm * 32 + (lane & 15)) * 80 + (lane >> 4) * 16);
    const uint32_t b_lane = (uint32_t)((wn * 64 + (lane & 7) + ((lane >> 4) & 1) * 8) * 80
                                       + ((lane >> 3) & 1) * 16);

    float acc[2][8][4];
#pragma unroll
    for (int i = 0; i < 2; i++)
#pragma unroll
        for (int n = 0; n < 8; n++)
#pragma unroll
            for (int j = 0; j < 4; j++) acc[i][n][j] = 0.f;

    load_stage(0);
    load_stage(1);

    for (int s = 0; s < 32; s++) {
        if (s + 2 < 32)      { load_stage(s + 2); cp_wait<2>(); }
        else if (s + 1 < 32) { cp_wait<1>(); }
        else                 { cp_wait<0>(); }
        __syncthreads();

        const uint32_t sbase = sb + (uint32_t)((s % 3) * STG3);
#pragma unroll
        for (int ks = 0; ks < 2; ks++) {
            const uint32_t ksb = ks * 32;
            uint32_t ah[2][4], al[2][4];
#pragma unroll
            for (int i = 0; i < 2; i++) {
                uint32_t base = sbase + a_lane + (uint32_t)(i * 16 * 80) + ksb;
                ldm_x4(ah[i], base);
                ldm_x4(al[i], base + 10240);
            }
#pragma unroll
            for (int p = 0; p < 4; p++) {
                uint32_t b[4];
                ldm_x4(b, sbase + 20480 + b_lane + (uint32_t)(p * 16 * 80) + ksb);
#pragma unroll
                for (int i = 0; i < 2; i++) {
                    mma_f16(acc[i][2 * p],     ah[i], b[0], b[1]);
                    mma_f16(acc[i][2 * p + 1], ah[i], b[2], b[3]);
                    mma_f16(acc[i][2 * p],     al[i], b[0], b[1]);
                    mma_f16(acc[i][2 * p + 1], al[i], b[2], b[3]);
                }
            }
        }
        __syncthreads();
    }

    const int er = lane >> 2, ec = (lane & 3) * 2;
#pragma unroll
    for (int i = 0; i < 2; i++) {
        const int rbase = row0 + wm * 32 + i * 16 + er;
#pragma unroll
        for (int n = 0; n < 8; n++) {
            const int cc = col0 + wn * 64 + n * 8 + ec;
            if (MODE == 0) {
                if (z == 0) {
#pragma unroll
                    for (int half = 0; half < 2; half++) {
                        float v0 = acc[i][n][2 * half], v1 = acc[i][n][2 * half + 1];
                        __half2 hv = __floats2half2_rn(v0, v1);
                        __half2 lv = __floats2half2_rn(v0 - __low2float(hv),
                                                       v1 - __high2float(hv));
                        size_t off = (size_t)(rbase + half * 8) * 1024 + cc;
                        *(__half2*)(Qh + off) = hv;
                        *(__half2*)(Ql + off) = lv;
                    }
                } else {
                    __half* dst = (z == 1) ? Ko : Vo;
#pragma unroll
                    for (int half = 0; half < 2; half++) {
                        size_t off = (size_t)(rbase + half * 8) * 1024 + cc;
                        *(__half2*)(dst + off) =
                            __floats2half2_rn(acc[i][n][2 * half], acc[i][n][2 * half + 1]);
                    }
                }
            } else {
                float b0 = bias[cc], b1 = bias[cc + 1];
                float2 lo_v = make_float2(acc[i][n][0] + b0, acc[i][n][1] + b1);
                float2 hi_v = make_float2(acc[i][n][2] + b0, acc[i][n][3] + b1);
                *(float2*)(C + (size_t)rbase * 1024 + cc)       = lo_v;
                *(float2*)(C + (size_t)(rbase + 8) * 1024 + cc) = hi_v;
            }
        }
    }
}

// ---------------------------------------------------------------------------
// HMMA flash attention (fp16x2: Q split / K single, P split / V single).
// CTA = (b, h, 128-row q tile); 8 warps, warp = 16 q rows x full 64 kv/d.
// launch_bounds(256,2): cap 125 regs to allow 2 CTAs/SM.
// Smem: Qh[128x144] Ql[128x144] | 2 stages x {K,V}[64x144] | mask
// ---------------------------------------------------------------------------
#define APITCH   144
#define AQ_SZ    18432
#define AKV_OFF  (2 * AQ_SZ)               // 36864
#define AKV_STG  18432                     // K 9216 + V 9216
#define AM_OFF   (AKV_OFF + 2 * AKV_STG)   // 73728
#define ATT_SMEM (AM_OFF + 512)

__global__ __launch_bounds__(256, 2) void attn_f16(const int* __restrict__ mask)
{
    extern __shared__ char sm[];
    const uint32_t sb = smem_u32(sm);
    const int t = threadIdx.x, lane = t & 31, w = t >> 5;
    const int q0 = blockIdx.x * 128, h = blockIdx.y, b = blockIdx.z;

    const size_t qoff  = (size_t)(b * LL + q0) * D_MODEL + h * HDIM;
    const size_t kvoff = (size_t)b * LL * D_MODEL + h * HDIM;
    const __half* kvsrc[2] = { g_K + kvoff, g_V + kvoff };

    {   // Q tile (once), committed with kv stage 0
        const __half* qsrc[2] = { g_Qh + qoff, g_Ql + qoff };
#pragma unroll
        for (int i = 0; i < 8; i++) {
            int idx = t + i * 256;
            int arr = idx >> 10, row = (idx >> 3) & 127, c = idx & 7;
            cp_async16(sb + arr * AQ_SZ + row * APITCH + c * 16,
                       qsrc[arr] + (size_t)row * D_MODEL + c * 8);
        }
    }
    auto load_kv = [&](int kt) {
        const uint32_t sbase = sb + AKV_OFF + (kt & 1) * AKV_STG;
#pragma unroll
        for (int i = 0; i < 4; i++) {
            int idx = t + i * 256;              // 0..1023
            int arr = idx >> 9, row = (idx >> 3) & 63, c = idx & 7;
            cp_async16(sbase + arr * 9216 + row * APITCH + c * 16,
                       kvsrc[arr] + (size_t)(kt * 64 + row) * D_MODEL + c * 8);
        }
        if (t < 64) {
            float bv = mask[b * LL + kt * 64 + t] ? 0.f : -1e30f;
            *(float*)(sm + AM_OFF + (kt & 1) * 256 + t * 4) = bv;
        }
        cp_commit();
    };
    load_kv(0);

    uint32_t qh[4][4], ql[4][4];
    float m0 = -1e30f, m1 = -1e30f, l0 = 0.f, l1 = 0.f;
    float O[8][4];
#pragma unroll
    for (int j = 0; j < 8; j++)
#pragma unroll
        for (int r = 0; r < 4; r++) O[j][r] = 0.f;

    const uint32_t a_addr =
        sb + (uint32_t)((w * 16 + (lane & 15)) * APITCH + (lane >> 4) * 16);
    const uint32_t k_lane =
        (uint32_t)(((lane & 7) + ((lane >> 4) & 1) * 8) * APITCH + ((lane >> 3) & 1) * 16);
    const uint32_t v_lane =
        (uint32_t)(((lane & 7) + ((lane >> 3) & 1) * 8) * APITCH + ((lane >> 4) & 1) * 16);

    for (int kt = 0; kt < LL / 64; kt++) {
        if (kt + 1 < LL / 64) { load_kv(kt + 1); cp_wait<1>(); }
        else                  { cp_wait<0>(); }
        __syncthreads();
        if (kt == 0) {
#pragma unroll
            for (int kd = 0; kd < 4; kd++) {
                ldm_x4(qh[kd], a_addr + kd * 32);
                ldm_x4(ql[kd], a_addr + AQ_SZ + kd * 32);
            }
        }
        const uint32_t kvb = sb + AKV_OFF + (kt & 1) * AKV_STG;

        // ---- S = Q K^T (fp16x2: (Qh+Ql) * K) ----
        float sc_[8][4];
#pragma unroll
        for (int j = 0; j < 8; j++)
#pragma unroll
            for (int r = 0; r < 4; r++) sc_[j][r] = 0.f;
#pragma unroll
        for (int kd = 0; kd < 4; kd++) {
#pragma unroll
            for (int g = 0; g < 4; g++) {
                uint32_t kb[4];
                ldm_x4(kb, kvb + k_lane + (uint32_t)(g * 16 * APITCH) + kd * 32);
                mma_f16(sc_[2 * g],     qh[kd], kb[0], kb[1]);
                mma_f16(sc_[2 * g + 1], qh[kd], kb[2], kb[3]);
                mma_f16(sc_[2 * g],     ql[kd], kb[0], kb[1]);
                mma_f16(sc_[2 * g + 1], ql[kd], kb[2], kb[3]);
            }
        }

        // ---- online softmax (rows r0 = lane>>2, r1 = r0+8) ----
        const uint32_t mb = sb + AM_OFF + (uint32_t)((kt & 1) * 256 + (lane & 3) * 8);
        float mt0 = -1e30f, mt1 = -1e30f;
#pragma unroll
        for (int j = 0; j < 8; j++) {
            float bx, by;
            asm volatile("ld.shared.v2.f32 {%0,%1}, [%2];"
                         : "=f"(bx), "=f"(by) : "r"(mb + j * 32));
            sc_[j][0] = fmaf(sc_[j][0], 0.125f, bx);
            sc_[j][1] = fmaf(sc_[j][1], 0.125f, by);
            sc_[j][2] = fmaf(sc_[j][2], 0.125f, bx);
            sc_[j][3] = fmaf(sc_[j][3], 0.125f, by);
            mt0 = fmaxf(mt0, fmaxf(sc_[j][0], sc_[j][1]));
            mt1 = fmaxf(mt1, fmaxf(sc_[j][2], sc_[j][3]));
        }
        mt0 = fmaxf(mt0, __shfl_xor_sync(0xffffffffu, mt0, 1));
        mt0 = fmaxf(mt0, __shfl_xor_sync(0xffffffffu, mt0, 2));
        mt1 = fmaxf(mt1, __shfl_xor_sync(0xffffffffu, mt1, 1));
        mt1 = fmaxf(mt1, __shfl_xor_sync(0xffffffffu, mt1, 2));
        const float m0n = fmaxf(m0, mt0), m1n = fmaxf(m1, mt1);
        const float e0 = __expf(m0 - m0n), e1 = __expf(m1 - m1n);
        m0 = m0n; m1 = m1n;
        float rs0 = 0.f, rs1 = 0.f;
#pragma unroll
        for (int j = 0; j < 8; j++) {
            float p0 = __expf(sc_[j][0] - m0n), p1 = __expf(sc_[j][1] - m0n);
            float p2 = __expf(sc_[j][2] - m1n), p3 = __expf(sc_[j][3] - m1n);
            sc_[j][0] = p0; sc_[j][1] = p1; sc_[j][2] = p2; sc_[j][3] = p3;
            rs0 += p0 + p1; rs1 += p2 + p3;
        }
        rs0 += __shfl_xor_sync(0xffffffffu, rs0, 1);
        rs0 += __shfl_xor_sync(0xffffffffu, rs0, 2);
        rs1 += __shfl_xor_sync(0xffffffffu, rs1, 1);
        rs1 += __shfl_xor_sync(0xffffffffu, rs1, 2);
        l0 = l0 * e0 + rs0; l1 = l1 * e1 + rs1;
#pragma unroll
        for (int j = 0; j < 8; j++) {
            O[j][0] *= e0; O[j][1] *= e0; O[j][2] *= e1; O[j][3] *= e1;
        }

        // ---- O += P V (fp16x2: (Ph+Pl) * V, P packed from registers) ----
#pragma unroll
        for (int tk = 0; tk < 4; tk++) {
            uint32_t pah[4], pal[4];
#pragma unroll
            for (int q = 0; q < 4; q++) {
                int j = 2 * tk + (q >> 1);
                float p0 = sc_[j][(q & 1) * 2], p1 = sc_[j][(q & 1) * 2 + 1];
                __half2 hv = __floats2half2_rn(p0, p1);
                __half2 lv = __floats2half2_rn(p0 - __low2float(hv),
                                               p1 - __high2float(hv));
                pah[q] = *(uint32_t*)&hv;
                pal[q] = *(uint32_t*)&lv;
            }
#pragma unroll
            for (int dg = 0; dg < 4; dg++) {
                uint32_t vb[4];
                ldm_x4_t(vb, kvb + 9216 + v_lane
                             + (uint32_t)(tk * 16 * APITCH) + dg * 32);
                mma_f16(O[2 * dg],     pah, vb[0], vb[1]);
                mma_f16(O[2 * dg + 1], pah, vb[2], vb[3]);
                mma_f16(O[2 * dg],     pal, vb[0], vb[1]);
                mma_f16(O[2 * dg + 1], pal, vb[2], vb[3]);
            }
        }
        __syncthreads();
    }

    // ---- epilogue: normalize, write ctx hi/lo split for the output GEMM ----
    const float inv0 = (m0 > -1e29f && l0 > 0.f) ? 1.f / l0 : 0.f;
    const float inv1 = (m1 > -1e29f && l1 > 0.f) ? 1.f / l1 : 0.f;
    const size_t r0 = (size_t)(b * LL + q0 + w * 16 + (lane >> 2));
    const int cb = h * HDIM + (lane & 3) * 2;
#pragma unroll
    for (int j = 0; j < 8; j++) {
        const int cc = cb + j * 8;
        {
            float v0 = O[j][0] * inv0, v1 = O[j][1] * inv0;
            __half2 hv = __floats2half2_rn(v0, v1);
            __half2 lv = __floats2half2_rn(v0 - __low2float(hv), v1 - __high2float(hv));
            *(__half2*)(g_Ahi + r0 * D_MODEL + cc) = hv;
            *(__half2*)(g_Alo + r0 * D_MODEL + cc) = lv;
        }
        {
            float v0 = O[j][2] * inv1, v1 = O[j][3] * inv1;
            __half2 hv = __floats2half2_rn(v0, v1);
            __half2 lv = __floats2half2_rn(v0 - __low2float(hv), v1 - __high2float(hv));
            *(__half2*)(g_Ahi + (r0 + 8) * D_MODEL + cc) = hv;
            *(__half2*)(g_Alo + (r0 + 8) * D_MODEL + cc) = lv;
        }
    }
}

// ---------------------------------------------------------------------------
extern "C" void kernel_launch(void* const* d_in, const int* in_sizes, int n_in,
                              void* d_out, int out_size)
{
    const float* q    = (const float*)d_in[0];
    const float* k    = (const float*)d_in[1];
    const float* v    = (const float*)d_in[2];
    const int*   mask = (const int*)  d_in[3];
    const float* Wq   = (const float*)d_in[4];
    const float* Wk   = (const float*)d_in[5];
    const float* Wv   = (const float*)d_in[6];
    const float* Wo   = (const float*)d_in[7];
    const float* bo   = (const float*)d_in[8];
    float*       out  = (float*)d_out;

    __half *gINh, *gINl, *gW3, *gWo, *gQh, *gQl, *gK, *gV, *gAhi, *gAlo;
    cudaGetSymbolAddress((void**)&gINh, g_INh);
    cudaGetSymbolAddress((void**)&gINl, g_INl);
    cudaGetSymbolAddress((void**)&gW3, g_W3);
    cudaGetSymbolAddress((void**)&gWo, g_Wo);
    cudaGetSymbolAddress((void**)&gQh, g_Qh);
    cudaGetSymbolAddress((void**)&gQl, g_Ql);
    cudaGetSymbolAddress((void**)&gK, g_K);
    cudaGetSymbolAddress((void**)&gV, g_V);
    cudaGetSymbolAddress((void**)&gAhi, g_Ahi);
    cudaGetSymbolAddress((void**)&gAlo, g_Alo);

    cudaFuncSetAttribute(hmma_f16<0>,
                         cudaFuncAttributeMaxDynamicSharedMemorySize, GSMEM3);
    cudaFuncSetAttribute(hmma_f16<1>,
                         cudaFuncAttributeMaxDynamicSharedMemorySize, GSMEM3);
    cudaFuncSetAttribute(attn_f16,
                         cudaFuncAttributeMaxDynamicSharedMemorySize, ATT_SMEM);

    const int n4i = MD / 4;
    const int n4w = DD / 4;

    // split x,k,v inputs (hi/lo) and convert weights (single fp16)
    split3_f16<<<dim3(n4i / 256, 1, 3), 256>>>(
        (const float4*)q, (const float4*)k, (const float4*)v,
        (__half2*)gINh, (__half2*)gINl, n4i, (size_t)MD / 2);
    cvt3_f16<<<dim3(n4w / 256, 1, 3), 256>>>(
        (const float4*)Wq, (const float4*)Wk, (const float4*)Wv,
        (__half2*)gW3, n4w, (size_t)DD / 2);
    cvt3_f16<<<dim3(n4w / 256, 1, 1), 256>>>(
        (const float4*)Wo, (const float4*)Wo, (const float4*)Wo,
        (__half2*)gWo, n4w, 0);

    // batched Q/K/V projections: grid (8, 32, 3), 2 CTAs/SM
    hmma_f16<0><<<dim3(D_MODEL / 128, MROWS / 128, 3), 256, GSMEM3>>>(
        gINh, gINl, gW3, gQh, gQl, gK, gV, nullptr, nullptr);

    // attention (writes ctx split into gAhi/gAlo)
    attn_f16<<<dim3(LL / 128, NHEADS, BB), 256, ATT_SMEM>>>(mask);

    // output projection (fp32 out + bias)
    hmma_f16<1><<<dim3(D_MODEL / 128, MROWS / 128, 1), 256, GSMEM3>>>(
        gAhi, gAlo, gWo, nullptr, nullptr, nullptr, nullptr, out, bo);
}